// round 2
// baseline (speedup 1.0000x reference)
#include <cuda_runtime.h>
#include <math.h>

// Problem constants
#define BB    64
#define HH    56
#define CC    384
#define NHEAD 12
#define HDIM  32
#define WSZ   7
#define SSFT  3
#define LW    49          // tokens per window
#define NWIN  4096        // total windows (64 per image * 64 images)
#define NTOK  200704      // B*H*W
#define TDIM  1152        // 3*C
#define FDIM  1536        // 4*C

// ---------------- scratch (device globals; reused across phases) --------------
// A: win (LN1 out, window order) -> attn out (window order) -> LN2 out
// B: qkv (window order, first NTOK*TDIM floats) -> gelu(mlp1)
// C: x2 = shortcut + proj (original order)
__device__ float g_bufA[(size_t)NTOK * CC];
__device__ float g_bufB[(size_t)NTOK * FDIM];
__device__ float g_bufC[(size_t)NTOK * CC];

// window-order row -> original-order row (same pixel for gather and scatter)
__device__ __forceinline__ int map_row(int r) {
    int n = r / LW, l = r - n * LW;
    int b = n >> 6, w = n & 63;
    int wh = w >> 3, ww = w & 7;
    int i = l / WSZ, j = l - i * WSZ;
    int hh = wh * WSZ + i;
    int hw = ww * WSZ + j;
    int oh = hh + SSFT; if (oh >= HH) oh -= HH;
    int ow = hw + SSFT; if (ow >= HH) ow -= HH;
    return b * (HH * HH) + oh * HH + ow;
}

__device__ __forceinline__ float gelu_f(float x) {
    return 0.5f * x * (1.0f + erff(x * 0.7071067811865476f));
}

// ---------------- LayerNorm (optionally gathering through the window map) -----
__global__ void ln_kernel(const float* __restrict__ x,
                          const float* __restrict__ gw,
                          const float* __restrict__ bw,
                          float* __restrict__ out, int gather)
{
    int r = blockIdx.x;
    int tid = threadIdx.x;                 // 128 threads
    int src = gather ? map_row(r) : r;
    const float* xr = x + (size_t)src * CC;
    float v0 = xr[tid], v1 = xr[tid + 128], v2 = xr[tid + 256];
    float s = v0 + v1 + v2;
    float q = v0 * v0 + v1 * v1 + v2 * v2;
    #pragma unroll
    for (int o = 16; o; o >>= 1) {
        s += __shfl_xor_sync(0xffffffffu, s, o);
        q += __shfl_xor_sync(0xffffffffu, q, o);
    }
    __shared__ float ss[4], sq[4];
    int w = tid >> 5;
    if ((tid & 31) == 0) { ss[w] = s; sq[w] = q; }
    __syncthreads();
    s = ss[0] + ss[1] + ss[2] + ss[3];
    q = sq[0] + sq[1] + sq[2] + sq[3];
    float mean = s * (1.0f / CC);
    float var  = q * (1.0f / CC) - mean * mean;
    float rstd = rsqrtf(var + 1e-5f);
    float* orow = out + (size_t)r * CC;
    orow[tid]       = (v0 - mean) * rstd * gw[tid]       + bw[tid];
    orow[tid + 128] = (v1 - mean) * rstd * gw[tid + 128] + bw[tid + 128];
    orow[tid + 256] = (v2 - mean) * rstd * gw[tid + 256] + bw[tid + 256];
}

// ---------------- windowed attention: one block per (window, head) ------------
__global__ __launch_bounds__(256) void attn_kernel(const float* __restrict__ qkv,
                                                   float* __restrict__ outp)
{
    int n = blockIdx.x;   // window
    int h = blockIdx.y;   // head
    __shared__ float qs[LW][HDIM + 1];
    __shared__ float ks[LW][HDIM + 1];
    __shared__ float vs[LW][HDIM + 1];
    __shared__ float sc[LW][LW + 1];
    __shared__ int   reg[LW];
    int tid = threadIdx.x;

    size_t base = (size_t)n * LW * TDIM + h * HDIM;
    for (int i = tid; i < LW * HDIM; i += 256) {
        int l = i >> 5, d = i & 31;
        size_t p = base + (size_t)l * TDIM + d;
        qs[l][d] = qkv[p];
        ks[l][d] = qkv[p + CC];
        vs[l][d] = qkv[p + 2 * CC];
    }
    if (tid < LW) {
        int w = n & 63;
        int wh = w >> 3, ww = w & 7;
        int i = tid / WSZ, j = tid - i * WSZ;
        int hh = wh * WSZ + i, hw = ww * WSZ + j;
        int rh = hh < 49 ? 0 : (hh < 53 ? 1 : 2);
        int rw = hw < 49 ? 0 : (hw < 53 ? 1 : 2);
        reg[tid] = rh * 3 + rw;
    }
    __syncthreads();

    const float scale = 0.17677669529663687f;  // 1/sqrt(32)
    for (int idx = tid; idx < LW * LW; idx += 256) {
        int l = idx / LW, m = idx - l * LW;
        float dot = 0.0f;
        #pragma unroll
        for (int d = 0; d < HDIM; d++) dot += qs[l][d] * ks[m][d];
        sc[l][m] = dot * scale + (reg[l] == reg[m] ? 0.0f : -100.0f);
    }
    __syncthreads();

    if (tid < LW) {
        float mx = -1e30f;
        #pragma unroll 7
        for (int m = 0; m < LW; m++) mx = fmaxf(mx, sc[tid][m]);
        float sum = 0.0f;
        #pragma unroll 7
        for (int m = 0; m < LW; m++) { float e = expf(sc[tid][m] - mx); sc[tid][m] = e; sum += e; }
        float inv = 1.0f / sum;
        #pragma unroll 7
        for (int m = 0; m < LW; m++) sc[tid][m] *= inv;
    }
    __syncthreads();

    for (int idx = tid; idx < LW * HDIM; idx += 256) {
        int l = idx >> 5, d = idx & 31;
        float acc = 0.0f;
        #pragma unroll
        for (int m = 0; m < LW; m++) acc += sc[l][m] * vs[m][d];
        outp[(size_t)(n * LW + l) * CC + h * HDIM + d] = acc;
    }
}

// ---------------- 128x128x8 fp32 SGEMM with fused epilogues -------------------
// EPI 0: out = acc + bias
// EPI 1: out[map_row(row)] = resid[map_row(row)] + acc + bias   (proj + scatter)
// EPI 2: out = gelu(acc + bias)
// EPI 3: out = acc + bias + resid[row]
template<int EPI>
__global__ __launch_bounds__(256) void sgemm_k(
    const float* __restrict__ A, const float* __restrict__ Bm,
    const float* __restrict__ bias, const float* __restrict__ resid,
    float* __restrict__ Cout, int M, int Nn, int K)
{
    __shared__ float As[8][128];
    __shared__ float Bs[8][128];
    int tid = threadIdx.x;
    int tx = tid & 15, ty = tid >> 4;
    int m0 = blockIdx.y * 128, n0 = blockIdx.x * 128;
    float acc[8][8] = {};

    int arow = tid >> 1;          // 0..127
    int akk  = (tid & 1) * 4;     // 0 or 4
    int brow = tid >> 5;          // 0..7
    int bcol = (tid & 31) * 4;
    const float* Ap = A + (size_t)(m0 + arow) * K + akk;
    const float* Bp = Bm + (size_t)brow * Nn + n0 + bcol;

    for (int k0 = 0; k0 < K; k0 += 8) {
        float4 av = *(const float4*)(Ap + k0);
        float4 bv = *(const float4*)(Bp + (size_t)k0 * Nn);
        As[akk + 0][arow] = av.x;
        As[akk + 1][arow] = av.y;
        As[akk + 2][arow] = av.z;
        As[akk + 3][arow] = av.w;
        *(float4*)(&Bs[brow][bcol]) = bv;
        __syncthreads();
        #pragma unroll
        for (int kk = 0; kk < 8; kk++) {
            float4 a0 = *(const float4*)&As[kk][ty * 4];
            float4 a1 = *(const float4*)&As[kk][64 + ty * 4];
            float4 b0 = *(const float4*)&Bs[kk][tx * 4];
            float4 b1 = *(const float4*)&Bs[kk][64 + tx * 4];
            float ra[8] = {a0.x, a0.y, a0.z, a0.w, a1.x, a1.y, a1.z, a1.w};
            float rb[8] = {b0.x, b0.y, b0.z, b0.w, b1.x, b1.y, b1.z, b1.w};
            #pragma unroll
            for (int i = 0; i < 8; i++)
                #pragma unroll
                for (int j = 0; j < 8; j++)
                    acc[i][j] = fmaf(ra[i], rb[j], acc[i][j]);
        }
        __syncthreads();
    }

    #pragma unroll
    for (int ii = 0; ii < 2; ii++) {
        #pragma unroll
        for (int i = 0; i < 4; i++) {
            int row = m0 + ii * 64 + ty * 4 + i;
            int orow = (EPI == 1) ? map_row(row) : row;
            #pragma unroll
            for (int jj = 0; jj < 2; jj++) {
                int col = n0 + jj * 64 + tx * 4;
                const float* a = &acc[ii * 4 + i][jj * 4];
                float4 r;
                r.x = a[0] + bias[col + 0];
                r.y = a[1] + bias[col + 1];
                r.z = a[2] + bias[col + 2];
                r.w = a[3] + bias[col + 3];
                if (EPI == 2) {
                    r.x = gelu_f(r.x); r.y = gelu_f(r.y);
                    r.z = gelu_f(r.z); r.w = gelu_f(r.w);
                }
                if (EPI == 1 || EPI == 3) {
                    size_t ridx = (size_t)orow * Nn + col;
                    float4 s = *(const float4*)&resid[ridx];
                    r.x += s.x; r.y += s.y; r.z += s.z; r.w += s.w;
                }
                *(float4*)&Cout[(size_t)orow * Nn + col] = r;
            }
        }
    }
}

// ------------------------------- launcher -------------------------------------
extern "C" void kernel_launch(void* const* d_in, const int* in_sizes, int n_in,
                              void* d_out, int out_size)
{
    const float* x      = (const float*)d_in[0];
    const float* g1     = (const float*)d_in[1];
    const float* bn1    = (const float*)d_in[2];
    const float* w_qkv  = (const float*)d_in[3];
    const float* b_qkv  = (const float*)d_in[4];
    const float* w_proj = (const float*)d_in[5];
    const float* b_proj = (const float*)d_in[6];
    const float* g2     = (const float*)d_in[7];
    const float* bn2    = (const float*)d_in[8];
    const float* w_mlp1 = (const float*)d_in[9];
    const float* b_mlp1 = (const float*)d_in[10];
    const float* w_mlp2 = (const float*)d_in[11];
    const float* b_mlp2 = (const float*)d_in[12];
    float* out = (float*)d_out;

    float *bufA, *bufB, *bufC;
    cudaGetSymbolAddress((void**)&bufA, g_bufA);
    cudaGetSymbolAddress((void**)&bufB, g_bufB);
    cudaGetSymbolAddress((void**)&bufC, g_bufC);

    // 1) LN1 + roll + window partition (gather): x -> A (win)
    ln_kernel<<<NTOK, 128>>>(x, g1, bn1, bufA, 1);

    // 2) QKV GEMM: A[NTOK,384] @ [384,1152] + bias -> B (qkv)
    sgemm_k<0><<<dim3(TDIM / 128, NTOK / 128), 256>>>(
        bufA, w_qkv, b_qkv, nullptr, bufB, NTOK, TDIM, CC);

    // 3) windowed attention with shift mask: B (qkv) -> A (o)
    attn_kernel<<<dim3(NWIN, NHEAD), 256>>>(bufB, bufA);

    // 4) proj GEMM + window reverse + roll back + shortcut residual: A -> C (x2)
    sgemm_k<1><<<dim3(CC / 128, NTOK / 128), 256>>>(
        bufA, w_proj, b_proj, x, bufC, NTOK, CC, CC);

    // 5) LN2: C -> A (ln2)
    ln_kernel<<<NTOK, 128>>>(bufC, g2, bn2, bufA, 0);

    // 6) MLP1 GEMM + exact GELU: A -> B (mlp)
    sgemm_k<2><<<dim3(FDIM / 128, NTOK / 128), 256>>>(
        bufA, w_mlp1, b_mlp1, nullptr, bufB, NTOK, FDIM, CC);

    // 7) MLP2 GEMM + residual: B (+C) -> out
    sgemm_k<3><<<dim3(CC / 128, NTOK / 128), 256>>>(
        bufB, w_mlp2, b_mlp2, bufC, out, NTOK, CC, FDIM);
}

// round 4
// speedup vs baseline: 1.3562x; 1.3562x over previous
#include <cuda_runtime.h>
#include <cuda_bf16.h>
#include <math.h>
#include <cstdint>

// Problem constants
#define BB    64
#define HH    56
#define CC    384
#define NHEAD 12
#define HDIM  32
#define WSZ   7
#define SSFT  3
#define LW    49
#define NWIN  4096
#define NTOK  200704
#define TDIM  1152
#define FDIM  1536

// ---------------- scratch ------------------------------------------------------
__device__ float g_bufA[(size_t)NTOK * CC];    // win -> attn-out -> ln2
__device__ float g_bufB[(size_t)NTOK * FDIM];  // qkv -> gelu(mlp1)
__device__ float g_bufC[(size_t)NTOK * CC];    // x2 residual
__device__ float g_wT[1769472];                // transposed weights (K-major)
#define WT_QKV  0
#define WT_PROJ 442368
#define WT_MLP1 589824
#define WT_MLP2 1179648

// ---------------- helpers ------------------------------------------------------
__device__ __forceinline__ uint32_t smem_u32(const void* p) {
    uint32_t a;
    asm("{ .reg .u64 t; cvta.to.shared.u64 t, %1; cvt.u32.u64 %0, t; }" : "=r"(a) : "l"(p));
    return a;
}

#define LDSM4(r, a) \
    asm volatile("ldmatrix.sync.aligned.m8n8.x4.shared.b16 {%0,%1,%2,%3}, [%4];" \
        : "=r"((r)[0]), "=r"((r)[1]), "=r"((r)[2]), "=r"((r)[3]) : "r"(a))

#define MMA_BF16(d, a, b) \
    asm volatile("mma.sync.aligned.m16n8k16.row.col.f32.bf16.bf16.f32 " \
        "{%0,%1,%2,%3},{%4,%5,%6,%7},{%8,%9},{%0,%1,%2,%3};" \
        : "+f"((d)[0]), "+f"((d)[1]), "+f"((d)[2]), "+f"((d)[3]) \
        : "r"((a)[0]), "r"((a)[1]), "r"((a)[2]), "r"((a)[3]), "r"((b)[0]), "r"((b)[1]))

__device__ __forceinline__ int map_row(int r) {
    int n = r / LW, l = r - n * LW;
    int b = n >> 6, w = n & 63;
    int wh = w >> 3, ww = w & 7;
    int i = l / WSZ, j = l - i * WSZ;
    int hh = wh * WSZ + i, hw = ww * WSZ + j;
    int oh = hh + SSFT; if (oh >= HH) oh -= HH;
    int ow = hw + SSFT; if (ow >= HH) ow -= HH;
    return b * (HH * HH) + oh * HH + ow;
}
__device__ __forceinline__ float gelu_f(float x) {
    return 0.5f * x * (1.0f + erff(x * 0.7071067811865476f));
}

// ---------------- weight transpose [K][N] -> [N][K] ----------------------------
__global__ void transpose_k(const float* __restrict__ src, float* __restrict__ dst,
                            int K, int N)
{
    __shared__ float t[32][33];
    int kb = blockIdx.y * 32, nb = blockIdx.x * 32;
    int tx = threadIdx.x, ty = threadIdx.y;  // 32x8
    #pragma unroll
    for (int i = ty; i < 32; i += 8) t[i][tx] = src[(size_t)(kb + i) * N + nb + tx];
    __syncthreads();
    #pragma unroll
    for (int i = ty; i < 32; i += 8) dst[(size_t)(nb + i) * K + kb + tx] = t[tx][i];
}

// ---------------- LayerNorm ----------------------------------------------------
__global__ void ln_kernel(const float* __restrict__ x,
                          const float* __restrict__ gw,
                          const float* __restrict__ bw,
                          float* __restrict__ out, int gather)
{
    int r = blockIdx.x;
    int tid = threadIdx.x;
    int src = gather ? map_row(r) : r;
    const float* xr = x + (size_t)src * CC;
    float v0 = xr[tid], v1 = xr[tid + 128], v2 = xr[tid + 256];
    float s = v0 + v1 + v2;
    float q = v0 * v0 + v1 * v1 + v2 * v2;
    #pragma unroll
    for (int o = 16; o; o >>= 1) {
        s += __shfl_xor_sync(0xffffffffu, s, o);
        q += __shfl_xor_sync(0xffffffffu, q, o);
    }
    __shared__ float ss[4], sq[4];
    int w = tid >> 5;
    if ((tid & 31) == 0) { ss[w] = s; sq[w] = q; }
    __syncthreads();
    s = ss[0] + ss[1] + ss[2] + ss[3];
    q = sq[0] + sq[1] + sq[2] + sq[3];
    float mean = s * (1.0f / CC);
    float var  = q * (1.0f / CC) - mean * mean;
    float rstd = rsqrtf(var + 1e-5f);
    float* orow = out + (size_t)r * CC;
    orow[tid]       = (v0 - mean) * rstd * gw[tid]       + bw[tid];
    orow[tid + 128] = (v1 - mean) * rstd * gw[tid + 128] + bw[tid + 128];
    orow[tid + 256] = (v2 - mean) * rstd * gw[tid + 256] + bw[tid + 256];
}

// ---------------- windowed attention ------------------------------------------
__global__ __launch_bounds__(256) void attn_kernel(const float* __restrict__ qkv,
                                                   float* __restrict__ outp)
{
    int n = blockIdx.x, h = blockIdx.y;
    __shared__ float qs[LW][HDIM + 1];
    __shared__ float ks[LW][HDIM + 1];
    __shared__ float vs[LW][HDIM + 1];
    __shared__ float sc[LW][LW + 1];
    __shared__ int   reg[LW];
    int tid = threadIdx.x;

    size_t base = (size_t)n * LW * TDIM + h * HDIM;
    for (int i = tid; i < LW * HDIM; i += 256) {
        int l = i >> 5, d = i & 31;
        size_t p = base + (size_t)l * TDIM + d;
        qs[l][d] = qkv[p];
        ks[l][d] = qkv[p + CC];
        vs[l][d] = qkv[p + 2 * CC];
    }
    if (tid < LW) {
        int w = n & 63;
        int wh = w >> 3, ww = w & 7;
        int i = tid / WSZ, j = tid - i * WSZ;
        int hh = wh * WSZ + i, hw = ww * WSZ + j;
        int rh = hh < 49 ? 0 : (hh < 53 ? 1 : 2);
        int rw = hw < 49 ? 0 : (hw < 53 ? 1 : 2);
        reg[tid] = rh * 3 + rw;
    }
    __syncthreads();

    const float scale = 0.17677669529663687f;
    for (int idx = tid; idx < LW * LW; idx += 256) {
        int l = idx / LW, m = idx - l * LW;
        float dot = 0.0f;
        #pragma unroll
        for (int d = 0; d < HDIM; d++) dot += qs[l][d] * ks[m][d];
        sc[l][m] = dot * scale + (reg[l] == reg[m] ? 0.0f : -100.0f);
    }
    __syncthreads();

    if (tid < LW) {
        float mx = -1e30f;
        #pragma unroll 7
        for (int m = 0; m < LW; m++) mx = fmaxf(mx, sc[tid][m]);
        float sum = 0.0f;
        #pragma unroll 7
        for (int m = 0; m < LW; m++) { float e = expf(sc[tid][m] - mx); sc[tid][m] = e; sum += e; }
        float inv = 1.0f / sum;
        #pragma unroll 7
        for (int m = 0; m < LW; m++) sc[tid][m] *= inv;
    }
    __syncthreads();

    for (int idx = tid; idx < LW * HDIM; idx += 256) {
        int l = idx >> 5, d = idx & 31;
        float acc = 0.0f;
        #pragma unroll
        for (int m = 0; m < LW; m++) acc += sc[l][m] * vs[m][d];
        outp[(size_t)(n * LW + l) * CC + h * HDIM + d] = acc;
    }
}

// ---------------- split-bf16 mma.sync GEMM 128x128x32 -------------------------
// smem stage: Ah[128x32] Al Bh Bl, each 128 rows x 80B pitch (32 bf16 + pad)
#define PITCH 80
#define TILEB (128 * PITCH)      // 10240
#define STAGEB (4 * TILEB)       // 40960
#define SMEMB (2 * STAGEB)       // 81920

template<int EPI>
__global__ __launch_bounds__(256) void hgemm(
    const float* __restrict__ A, const float* __restrict__ BT,
    const float* __restrict__ bias, const float* __restrict__ resid,
    float* __restrict__ Cout, int Nn, int K)
{
    extern __shared__ char smem[];
    uint32_t sb = smem_u32(smem);
    int tid = threadIdx.x;
    int lane = tid & 31, warp = tid >> 5;
    int wm = warp >> 2, wn = warp & 3;        // warp tile: 64 (m) x 32 (n)
    int m0 = blockIdx.y * 128, n0 = blockIdx.x * 128;

    const float* Ap = A  + (size_t)(m0 + (tid >> 1)) * K + (tid & 1) * 16;
    const float* Bp = BT + (size_t)(n0 + (tid >> 1)) * K + (tid & 1) * 16;
    uint32_t soff = (uint32_t)(tid >> 1) * PITCH + (uint32_t)(tid & 1) * 32;

    float acc[4][4][4];
    #pragma unroll
    for (int i = 0; i < 4; i++)
        #pragma unroll
        for (int j = 0; j < 4; j++)
            #pragma unroll
            for (int e = 0; e < 4; e++) acc[i][j][e] = 0.0f;

    float4 pa[4], pb[4];
    #pragma unroll
    for (int q = 0; q < 4; q++) {
        pa[q] = *(const float4*)(Ap + q * 4);
        pb[q] = *(const float4*)(Bp + q * 4);
    }

    // per-thread ldmatrix base offsets (within a stage)
    uint32_t aoff = (uint32_t)(wm * 64 + (lane & 15)) * PITCH + (uint32_t)(lane >> 4) * 16;
    uint32_t boff = 2 * TILEB + (uint32_t)(wn * 32 + (lane & 15)) * PITCH + (uint32_t)(lane >> 4) * 16;

    int NC = K / 32;

    // store chunk 0 into stage 0
    {
        char* st = smem;
        #pragma unroll
        for (int q = 0; q < 4; q++) {
            float4 av = pa[q], bv = pb[q];
            __nv_bfloat162 ah01 = __floats2bfloat162_rn(av.x, av.y);
            __nv_bfloat162 ah23 = __floats2bfloat162_rn(av.z, av.w);
            __nv_bfloat162 al01 = __floats2bfloat162_rn(av.x - __bfloat162float(ah01.x), av.y - __bfloat162float(ah01.y));
            __nv_bfloat162 al23 = __floats2bfloat162_rn(av.z - __bfloat162float(ah23.x), av.w - __bfloat162float(ah23.y));
            __nv_bfloat162 bh01 = __floats2bfloat162_rn(bv.x, bv.y);
            __nv_bfloat162 bh23 = __floats2bfloat162_rn(bv.z, bv.w);
            __nv_bfloat162 bl01 = __floats2bfloat162_rn(bv.x - __bfloat162float(bh01.x), bv.y - __bfloat162float(bh01.y));
            __nv_bfloat162 bl23 = __floats2bfloat162_rn(bv.z - __bfloat162float(bh23.x), bv.w - __bfloat162float(bh23.y));
            uint2 hA = make_uint2(*(uint32_t*)&ah01, *(uint32_t*)&ah23);
            uint2 lA = make_uint2(*(uint32_t*)&al01, *(uint32_t*)&al23);
            uint2 hB = make_uint2(*(uint32_t*)&bh01, *(uint32_t*)&bh23);
            uint2 lB = make_uint2(*(uint32_t*)&bl01, *(uint32_t*)&bl23);
            *(uint2*)(st + soff + q * 8)             = hA;
            *(uint2*)(st + TILEB + soff + q * 8)     = lA;
            *(uint2*)(st + 2 * TILEB + soff + q * 8) = hB;
            *(uint2*)(st + 3 * TILEB + soff + q * 8) = lB;
        }
    }
    __syncthreads();

    for (int c = 0; c < NC; c++) {
        int bsel = c & 1;
        if (c + 1 < NC) {
            const float* ap = Ap + (c + 1) * 32;
            const float* bp = Bp + (c + 1) * 32;
            #pragma unroll
            for (int q = 0; q < 4; q++) {
                pa[q] = *(const float4*)(ap + q * 4);
                pb[q] = *(const float4*)(bp + q * 4);
            }
        }
        // ---- mma over stage bsel ----
        uint32_t sA = sb + bsel * STAGEB + aoff;
        uint32_t sB = sb + bsel * STAGEB + boff;
        #pragma unroll
        for (int kk = 0; kk < 2; kk++) {
            uint32_t ka = sA + kk * 32;
            uint32_t kb = sB + kk * 32;
            uint32_t ah[4][4], al[4][4];
            #pragma unroll
            for (int i = 0; i < 4; i++) {
                LDSM4(ah[i], ka + i * 16 * PITCH);
                LDSM4(al[i], ka + TILEB + i * 16 * PITCH);
            }
            uint32_t bh[4][2], bl[4][2];
            #pragma unroll
            for (int g = 0; g < 2; g++) {
                uint32_t r[4];
                LDSM4(r, kb + g * 16 * PITCH);
                bh[2 * g][0] = r[0]; bh[2 * g][1] = r[2];
                bh[2 * g + 1][0] = r[1]; bh[2 * g + 1][1] = r[3];
                LDSM4(r, kb + TILEB + g * 16 * PITCH);
                bl[2 * g][0] = r[0]; bl[2 * g][1] = r[2];
                bl[2 * g + 1][0] = r[1]; bl[2 * g + 1][1] = r[3];
            }
            #pragma unroll
            for (int i = 0; i < 4; i++)
                #pragma unroll
                for (int j = 0; j < 4; j++)
                    MMA_BF16(acc[i][j], ah[i], bh[j]);
            #pragma unroll
            for (int i = 0; i < 4; i++)
                #pragma unroll
                for (int j = 0; j < 4; j++)
                    MMA_BF16(acc[i][j], ah[i], bl[j]);
            #pragma unroll
            for (int i = 0; i < 4; i++)
                #pragma unroll
                for (int j = 0; j < 4; j++)
                    MMA_BF16(acc[i][j], al[i], bh[j]);
        }
        // ---- store chunk c+1 into stage 1-bsel ----
        if (c + 1 < NC) {
            char* st = smem + (1 - bsel) * STAGEB;
            #pragma unroll
            for (int q = 0; q < 4; q++) {
                float4 av = pa[q], bv = pb[q];
                __nv_bfloat162 ah01 = __floats2bfloat162_rn(av.x, av.y);
                __nv_bfloat162 ah23 = __floats2bfloat162_rn(av.z, av.w);
                __nv_bfloat162 al01 = __floats2bfloat162_rn(av.x - __bfloat162float(ah01.x), av.y - __bfloat162float(ah01.y));
                __nv_bfloat162 al23 = __floats2bfloat162_rn(av.z - __bfloat162float(ah23.x), av.w - __bfloat162float(ah23.y));
                __nv_bfloat162 bh01 = __floats2bfloat162_rn(bv.x, bv.y);
                __nv_bfloat162 bh23 = __floats2bfloat162_rn(bv.z, bv.w);
                __nv_bfloat162 bl01 = __floats2bfloat162_rn(bv.x - __bfloat162float(bh01.x), bv.y - __bfloat162float(bh01.y));
                __nv_bfloat162 bl23 = __floats2bfloat162_rn(bv.z - __bfloat162float(bh23.x), bv.w - __bfloat162float(bh23.y));
                uint2 hA = make_uint2(*(uint32_t*)&ah01, *(uint32_t*)&ah23);
                uint2 lA = make_uint2(*(uint32_t*)&al01, *(uint32_t*)&al23);
                uint2 hB = make_uint2(*(uint32_t*)&bh01, *(uint32_t*)&bh23);
                uint2 lB = make_uint2(*(uint32_t*)&bl01, *(uint32_t*)&bl23);
                *(uint2*)(st + soff + q * 8)             = hA;
                *(uint2*)(st + TILEB + soff + q * 8)     = lA;
                *(uint2*)(st + 2 * TILEB + soff + q * 8) = hB;
                *(uint2*)(st + 3 * TILEB + soff + q * 8) = lB;
            }
        }
        __syncthreads();
    }

    // ---- epilogue ----
    int lr = lane >> 2;           // row within 8-row group
    int lc = (lane & 3) * 2;      // col pair
    #pragma unroll
    for (int i = 0; i < 4; i++) {
        int gr0 = m0 + wm * 64 + i * 16 + lr;
        int gr1 = gr0 + 8;
        int or0 = (EPI == 1) ? map_row(gr0) : gr0;
        int or1 = (EPI == 1) ? map_row(gr1) : gr1;
        float* c0 = Cout + (size_t)or0 * Nn;
        float* c1 = Cout + (size_t)or1 * Nn;
        const float* r0p = (EPI == 1 || EPI == 3) ? resid + (size_t)or0 * Nn : nullptr;
        const float* r1p = (EPI == 1 || EPI == 3) ? resid + (size_t)or1 * Nn : nullptr;
        #pragma unroll
        for (int j = 0; j < 4; j++) {
            int cb = n0 + wn * 32 + j * 8 + lc;
            float b0 = bias[cb], b1 = bias[cb + 1];
            float v00 = acc[i][j][0] + b0, v01 = acc[i][j][1] + b1;
            float v10 = acc[i][j][2] + b0, v11 = acc[i][j][3] + b1;
            if (EPI == 2) {
                v00 = gelu_f(v00); v01 = gelu_f(v01);
                v10 = gelu_f(v10); v11 = gelu_f(v11);
            }
            if (EPI == 1 || EPI == 3) {
                float2 s0 = *(const float2*)(r0p + cb);
                float2 s1 = *(const float2*)(r1p + cb);
                v00 += s0.x; v01 += s0.y;
                v10 += s1.x; v11 += s1.y;
            }
            *(float2*)(c0 + cb) = make_float2(v00, v01);
            *(float2*)(c1 + cb) = make_float2(v10, v11);
        }
    }
}

// ------------------------------- launcher -------------------------------------
extern "C" void kernel_launch(void* const* d_in, const int* in_sizes, int n_in,
                              void* d_out, int out_size)
{
    const float* x      = (const float*)d_in[0];
    const float* g1     = (const float*)d_in[1];
    const float* bn1    = (const float*)d_in[2];
    const float* w_qkv  = (const float*)d_in[3];
    const float* b_qkv  = (const float*)d_in[4];
    const float* w_proj = (const float*)d_in[5];
    const float* b_proj = (const float*)d_in[6];
    const float* g2     = (const float*)d_in[7];
    const float* bn2    = (const float*)d_in[8];
    const float* w_mlp1 = (const float*)d_in[9];
    const float* b_mlp1 = (const float*)d_in[10];
    const float* w_mlp2 = (const float*)d_in[11];
    const float* b_mlp2 = (const float*)d_in[12];
    float* out = (float*)d_out;

    float *bufA, *bufB, *bufC, *wT;
    cudaGetSymbolAddress((void**)&bufA, g_bufA);
    cudaGetSymbolAddress((void**)&bufB, g_bufB);
    cudaGetSymbolAddress((void**)&bufC, g_bufC);
    cudaGetSymbolAddress((void**)&wT,   g_wT);

    cudaFuncSetAttribute(hgemm<0>, cudaFuncAttributeMaxDynamicSharedMemorySize, SMEMB);
    cudaFuncSetAttribute(hgemm<1>, cudaFuncAttributeMaxDynamicSharedMemorySize, SMEMB);
    cudaFuncSetAttribute(hgemm<2>, cudaFuncAttributeMaxDynamicSharedMemorySize, SMEMB);
    cudaFuncSetAttribute(hgemm<3>, cudaFuncAttributeMaxDynamicSharedMemorySize, SMEMB);

    // 0) transpose weights to K-major
    transpose_k<<<dim3(TDIM / 32, CC / 32), dim3(32, 8)>>>(w_qkv,  wT + WT_QKV,  CC, TDIM);
    transpose_k<<<dim3(CC / 32, CC / 32),   dim3(32, 8)>>>(w_proj, wT + WT_PROJ, CC, CC);
    transpose_k<<<dim3(FDIM / 32, CC / 32), dim3(32, 8)>>>(w_mlp1, wT + WT_MLP1, CC, FDIM);
    transpose_k<<<dim3(CC / 32, FDIM / 32), dim3(32, 8)>>>(w_mlp2, wT + WT_MLP2, FDIM, CC);

    // 1) LN1 + roll + window partition
    ln_kernel<<<NTOK, 128>>>(x, g1, bn1, bufA, 1);

    // 2) QKV GEMM
    hgemm<0><<<dim3(TDIM / 128, NTOK / 128), 256, SMEMB>>>(
        bufA, wT + WT_QKV, b_qkv, nullptr, bufB, TDIM, CC);

    // 3) attention
    attn_kernel<<<dim3(NWIN, NHEAD), 256>>>(bufB, bufA);

    // 4) proj + scatter + shortcut
    hgemm<1><<<dim3(CC / 128, NTOK / 128), 256, SMEMB>>>(
        bufA, wT + WT_PROJ, b_proj, x, bufC, CC, CC);

    // 5) LN2
    ln_kernel<<<NTOK, 128>>>(bufC, g2, bn2, bufA, 0);

    // 6) MLP1 + GELU
    hgemm<2><<<dim3(FDIM / 128, NTOK / 128), 256, SMEMB>>>(
        bufA, wT + WT_MLP1, b_mlp1, nullptr, bufB, FDIM, CC);

    // 7) MLP2 + residual
    hgemm<3><<<dim3(CC / 128, NTOK / 128), 256, SMEMB>>>(
        bufB, wT + WT_MLP2, b_mlp2, bufC, out, CC, FDIM);
}

// round 5
// speedup vs baseline: 1.9589x; 1.4444x over previous
#include <cuda_runtime.h>
#include <cuda_bf16.h>
#include <math.h>
#include <cstdint>

// Problem constants
#define BB    64
#define HH    56
#define CC    384
#define NHEAD 12
#define HDIM  32
#define WSZ   7
#define SSFT  3
#define LW    49
#define NWIN  4096
#define NTOK  200704
#define TDIM  1152
#define FDIM  1536

// ---------------- scratch ------------------------------------------------------
// A-operand split pair (ln1 out -> attn out -> ln2 out)
__device__ uint16_t g_ahi[(size_t)NTOK * CC];
__device__ uint16_t g_alo[(size_t)NTOK * CC];
// big union buffer: qkv fp32 (steps 2-3) OR gelu hi+lo (steps 6-7)
__device__ __align__(16) unsigned char g_big[(size_t)NTOK * FDIM * 4];
// x2 residual fp32
__device__ float g_x2[(size_t)NTOK * CC];
// split weights, K-major
__device__ uint16_t g_whi[1769472];
__device__ uint16_t g_wlo[1769472];
#define WT_QKV  0
#define WT_PROJ 442368
#define WT_MLP1 589824
#define WT_MLP2 1179648

// ---------------- helpers ------------------------------------------------------
__device__ __forceinline__ uint32_t smem_u32(const void* p) {
    uint32_t a;
    asm("{ .reg .u64 t; cvta.to.shared.u64 t, %1; cvt.u32.u64 %0, t; }" : "=r"(a) : "l"(p));
    return a;
}
#define LDSM4(r, a) \
    asm volatile("ldmatrix.sync.aligned.m8n8.x4.shared.b16 {%0,%1,%2,%3}, [%4];" \
        : "=r"((r)[0]), "=r"((r)[1]), "=r"((r)[2]), "=r"((r)[3]) : "r"(a))
#define MMA_BF16(d, a, b) \
    asm volatile("mma.sync.aligned.m16n8k16.row.col.f32.bf16.bf16.f32 " \
        "{%0,%1,%2,%3},{%4,%5,%6,%7},{%8,%9},{%0,%1,%2,%3};" \
        : "+f"((d)[0]), "+f"((d)[1]), "+f"((d)[2]), "+f"((d)[3]) \
        : "r"((a)[0]), "r"((a)[1]), "r"((a)[2]), "r"((a)[3]), "r"((b)[0]), "r"((b)[1]))
#define CP16(d, s) do { \
    unsigned long long _g = __cvta_generic_to_global((const void*)(s)); \
    asm volatile("cp.async.cg.shared.global [%0], [%1], 16;" :: "r"(d), "l"(_g) : "memory"); \
} while (0)
#define CP_COMMIT() asm volatile("cp.async.commit_group;" ::: "memory")
#define CP_WAIT1()  asm volatile("cp.async.wait_group 1;" ::: "memory")

__device__ __forceinline__ int map_row(int r) {
    int n = r / LW, l = r - n * LW;
    int b = n >> 6, w = n & 63;
    int wh = w >> 3, ww = w & 7;
    int i = l / WSZ, j = l - i * WSZ;
    int hh = wh * WSZ + i, hw = ww * WSZ + j;
    int oh = hh + SSFT; if (oh >= HH) oh -= HH;
    int ow = hw + SSFT; if (ow >= HH) ow -= HH;
    return b * (HH * HH) + oh * HH + ow;
}
__device__ __forceinline__ float gelu_f(float x) {
    return 0.5f * x * (1.0f + erff(x * 0.7071067811865476f));
}
__device__ __forceinline__ uint16_t bf_bits(__nv_bfloat16 h) {
    return *(uint16_t*)&h;
}
__device__ __forceinline__ void split_bf(float v, uint16_t& hi, uint16_t& lo) {
    __nv_bfloat16 h = __float2bfloat16(v);
    hi = bf_bits(h);
    lo = bf_bits(__float2bfloat16(v - __bfloat162float(h)));
}
// swizzled 16B-unit offset within an 8KB tile (128 rows x 64B)
__device__ __forceinline__ uint32_t swz(uint32_t row, uint32_t cb2) {
    return row * 64 + ((cb2 ^ ((row >> 1) & 3)) << 4);
}

// ---------------- weight transpose + split: [K][N] fp32 -> [N][K] bf16 hi/lo ---
__global__ void transpose_k(const float* __restrict__ src,
                            uint16_t* __restrict__ dhi, uint16_t* __restrict__ dlo,
                            int K, int N)
{
    __shared__ float t[32][33];
    int kb = blockIdx.y * 32, nb = blockIdx.x * 32;
    int tx = threadIdx.x, ty = threadIdx.y;  // 32x8
    #pragma unroll
    for (int i = ty; i < 32; i += 8) t[i][tx] = src[(size_t)(kb + i) * N + nb + tx];
    __syncthreads();
    #pragma unroll
    for (int i = ty; i < 32; i += 8) {
        float v = t[tx][i];
        uint16_t hi, lo;
        split_bf(v, hi, lo);
        size_t idx = (size_t)(nb + i) * K + kb + tx;
        dhi[idx] = hi;
        dlo[idx] = lo;
    }
}

// ---------------- LayerNorm -> split bf16 --------------------------------------
__global__ void ln_kernel(const float* __restrict__ x,
                          const float* __restrict__ gw,
                          const float* __restrict__ bw,
                          uint16_t* __restrict__ ohi, uint16_t* __restrict__ olo,
                          int gather)
{
    int r = blockIdx.x;
    int tid = threadIdx.x;
    int src = gather ? map_row(r) : r;
    const float* xr = x + (size_t)src * CC;
    float v0 = xr[tid], v1 = xr[tid + 128], v2 = xr[tid + 256];
    float s = v0 + v1 + v2;
    float q = v0 * v0 + v1 * v1 + v2 * v2;
    #pragma unroll
    for (int o = 16; o; o >>= 1) {
        s += __shfl_xor_sync(0xffffffffu, s, o);
        q += __shfl_xor_sync(0xffffffffu, q, o);
    }
    __shared__ float ss[4], sq[4];
    int w = tid >> 5;
    if ((tid & 31) == 0) { ss[w] = s; sq[w] = q; }
    __syncthreads();
    s = ss[0] + ss[1] + ss[2] + ss[3];
    q = sq[0] + sq[1] + sq[2] + sq[3];
    float mean = s * (1.0f / CC);
    float var  = q * (1.0f / CC) - mean * mean;
    float rstd = rsqrtf(var + 1e-5f);
    size_t base = (size_t)r * CC;
    #pragma unroll
    for (int e = 0; e < 3; e++) {
        int col = tid + e * 128;
        float v = (e == 0 ? v0 : (e == 1 ? v1 : v2));
        float y = (v - mean) * rstd * gw[col] + bw[col];
        uint16_t hi, lo;
        split_bf(y, hi, lo);
        ohi[base + col] = hi;
        olo[base + col] = lo;
    }
}

// ---------------- windowed attention (fp32 in, split bf16 out) -----------------
__global__ __launch_bounds__(256) void attn_kernel(const float* __restrict__ qkv,
                                                   uint16_t* __restrict__ ohi,
                                                   uint16_t* __restrict__ olo)
{
    int n = blockIdx.x, h = blockIdx.y;
    __shared__ float qs[LW][HDIM + 1];
    __shared__ float ks[LW][HDIM + 1];
    __shared__ float vs[LW][HDIM + 1];
    __shared__ float sc[LW][LW + 1];
    __shared__ int   reg[LW];
    int tid = threadIdx.x;

    size_t base = (size_t)n * LW * TDIM + h * HDIM;
    for (int i = tid; i < LW * HDIM; i += 256) {
        int l = i >> 5, d = i & 31;
        size_t p = base + (size_t)l * TDIM + d;
        qs[l][d] = qkv[p];
        ks[l][d] = qkv[p + CC];
        vs[l][d] = qkv[p + 2 * CC];
    }
    if (tid < LW) {
        int w = n & 63;
        int wh = w >> 3, ww = w & 7;
        int i = tid / WSZ, j = tid - i * WSZ;
        int hh = wh * WSZ + i, hw = ww * WSZ + j;
        int rh = hh < 49 ? 0 : (hh < 53 ? 1 : 2);
        int rw = hw < 49 ? 0 : (hw < 53 ? 1 : 2);
        reg[tid] = rh * 3 + rw;
    }
    __syncthreads();

    const float scale = 0.17677669529663687f;
    for (int idx = tid; idx < LW * LW; idx += 256) {
        int l = idx / LW, m = idx - l * LW;
        float dot = 0.0f;
        #pragma unroll
        for (int d = 0; d < HDIM; d++) dot += qs[l][d] * ks[m][d];
        sc[l][m] = dot * scale + (reg[l] == reg[m] ? 0.0f : -100.0f);
    }
    __syncthreads();

    if (tid < LW) {
        float mx = -1e30f;
        #pragma unroll 7
        for (int m = 0; m < LW; m++) mx = fmaxf(mx, sc[tid][m]);
        float sum = 0.0f;
        #pragma unroll 7
        for (int m = 0; m < LW; m++) { float e = expf(sc[tid][m] - mx); sc[tid][m] = e; sum += e; }
        float inv = 1.0f / sum;
        #pragma unroll 7
        for (int m = 0; m < LW; m++) sc[tid][m] *= inv;
    }
    __syncthreads();

    for (int idx = tid; idx < LW * HDIM; idx += 256) {
        int l = idx >> 5, d = idx & 31;
        float acc = 0.0f;
        #pragma unroll
        for (int m = 0; m < LW; m++) acc += sc[l][m] * vs[m][d];
        size_t o = (size_t)(n * LW + l) * CC + h * HDIM + d;
        uint16_t hi, lo;
        split_bf(acc, hi, lo);
        ohi[o] = hi;
        olo[o] = lo;
    }
}

// ---------------- split-bf16 mma.sync GEMM 128x128x32, cp.async 3-stage --------
// stage layout: Ah[8KB] Al[8KB] Bh[8KB] Bl[8KB] = 32KB; 3 stages = 96KB
#define TILE8K 8192
#define STAGEB 32768
#define SMEMB  98304

// EPI 0: fp32 out = acc + bias                       (QKV)
// EPI 1: fp32 out[map_row] = resid[map_row]+acc+bias (proj scatter)
// EPI 2: split bf16 out = gelu(acc + bias)           (MLP1)
// EPI 3: fp32 out = acc + bias + resid               (MLP2 final)
template<int EPI>
__global__ __launch_bounds__(256) void hgemm(
    const uint16_t* __restrict__ Ah, const uint16_t* __restrict__ Al,
    const uint16_t* __restrict__ Bh, const uint16_t* __restrict__ Bl,
    const float* __restrict__ bias, const float* __restrict__ resid,
    float* __restrict__ Cout, uint16_t* __restrict__ OutHi, uint16_t* __restrict__ OutLo,
    int Nn, int K)
{
    extern __shared__ char smem[];
    uint32_t sb = smem_u32(smem);
    int tid = threadIdx.x;
    int lane = tid & 31, warp = tid >> 5;
    int wm = warp >> 2, wn = warp & 3;        // warp tile: 64(m) x 32(n)
    int m0 = blockIdx.y * 128, n0 = blockIdx.x * 128;

    const uint16_t* srcs[4] = {
        Ah + (size_t)m0 * K, Al + (size_t)m0 * K,
        Bh + (size_t)n0 * K, Bl + (size_t)n0 * K
    };

    float acc[4][4][4];
    #pragma unroll
    for (int i = 0; i < 4; i++)
        #pragma unroll
        for (int j = 0; j < 4; j++)
            #pragma unroll
            for (int e = 0; e < 4; e++) acc[i][j][e] = 0.0f;

    int NC = K / 32;

    // issue loads for a chunk into a stage
    auto load_stage = [&](int stg, int c) {
        uint32_t sdst = sb + stg * STAGEB;
        #pragma unroll
        for (int i = 0; i < 8; i++) {
            int tile = i >> 1;
            int w = tid + ((i & 1) << 8);
            int r = w >> 2, cb = w & 3;
            uint32_t d = sdst + tile * TILE8K + swz(r, cb);
            const uint16_t* s = srcs[tile] + (size_t)r * K + c * 32 + cb * 8;
            CP16(d, s);
        }
        CP_COMMIT();
    };

    load_stage(0, 0);
    load_stage(1, 1);

    int cs = 0;
    for (int c = 0; c < NC; c++) {
        CP_WAIT1();
        __syncthreads();
        if (c + 2 < NC) {
            int s2 = cs + 2; if (s2 >= 3) s2 -= 3;
            load_stage(s2, c + 2);
        }
        uint32_t sbs = sb + cs * STAGEB;
        #pragma unroll
        for (int kk = 0; kk < 2; kk++) {
            uint32_t cb2 = (uint32_t)(kk * 2 + (lane >> 4));
            uint32_t ah[4][4], al[4][4];
            #pragma unroll
            for (int i = 0; i < 4; i++) {
                uint32_t row = (uint32_t)(wm * 64 + i * 16 + (lane & 15));
                LDSM4(ah[i], sbs + swz(row, cb2));
                LDSM4(al[i], sbs + TILE8K + swz(row, cb2));
            }
            uint32_t bh[4][2], bl[4][2];
            #pragma unroll
            for (int g = 0; g < 2; g++) {
                uint32_t row = (uint32_t)(wn * 32 + g * 16 + (lane & 15));
                uint32_t r[4];
                LDSM4(r, sbs + 2 * TILE8K + swz(row, cb2));
                bh[2 * g][0] = r[0]; bh[2 * g][1] = r[2];
                bh[2 * g + 1][0] = r[1]; bh[2 * g + 1][1] = r[3];
                LDSM4(r, sbs + 3 * TILE8K + swz(row, cb2));
                bl[2 * g][0] = r[0]; bl[2 * g][1] = r[2];
                bl[2 * g + 1][0] = r[1]; bl[2 * g + 1][1] = r[3];
            }
            #pragma unroll
            for (int i = 0; i < 4; i++)
                #pragma unroll
                for (int j = 0; j < 4; j++)
                    MMA_BF16(acc[i][j], ah[i], bh[j]);
            #pragma unroll
            for (int i = 0; i < 4; i++)
                #pragma unroll
                for (int j = 0; j < 4; j++)
                    MMA_BF16(acc[i][j], ah[i], bl[j]);
            #pragma unroll
            for (int i = 0; i < 4; i++)
                #pragma unroll
                for (int j = 0; j < 4; j++)
                    MMA_BF16(acc[i][j], al[i], bh[j]);
        }
        cs++; if (cs >= 3) cs = 0;
    }

    // ---- epilogue ----
    int lr = lane >> 2;
    int lc = (lane & 3) * 2;
    #pragma unroll
    for (int i = 0; i < 4; i++) {
        int gr0 = m0 + wm * 64 + i * 16 + lr;
        int gr1 = gr0 + 8;
        int or0 = (EPI == 1) ? map_row(gr0) : gr0;
        int or1 = (EPI == 1) ? map_row(gr1) : gr1;
        const float* r0p = (EPI == 1 || EPI == 3) ? resid + (size_t)or0 * Nn : nullptr;
        const float* r1p = (EPI == 1 || EPI == 3) ? resid + (size_t)or1 * Nn : nullptr;
        #pragma unroll
        for (int j = 0; j < 4; j++) {
            int cb = n0 + wn * 32 + j * 8 + lc;
            float b0 = bias[cb], b1 = bias[cb + 1];
            float v00 = acc[i][j][0] + b0, v01 = acc[i][j][1] + b1;
            float v10 = acc[i][j][2] + b0, v11 = acc[i][j][3] + b1;
            if (EPI == 2) {
                v00 = gelu_f(v00); v01 = gelu_f(v01);
                v10 = gelu_f(v10); v11 = gelu_f(v11);
                uint16_t h00, l00, h01, l01, h10, l10, h11, l11;
                split_bf(v00, h00, l00); split_bf(v01, h01, l01);
                split_bf(v10, h10, l10); split_bf(v11, h11, l11);
                *(uint32_t*)(OutHi + (size_t)or0 * Nn + cb) = (uint32_t)h00 | ((uint32_t)h01 << 16);
                *(uint32_t*)(OutLo + (size_t)or0 * Nn + cb) = (uint32_t)l00 | ((uint32_t)l01 << 16);
                *(uint32_t*)(OutHi + (size_t)or1 * Nn + cb) = (uint32_t)h10 | ((uint32_t)h11 << 16);
                *(uint32_t*)(OutLo + (size_t)or1 * Nn + cb) = (uint32_t)l10 | ((uint32_t)l11 << 16);
            } else {
                if (EPI == 1 || EPI == 3) {
                    float2 s0 = *(const float2*)(r0p + cb);
                    float2 s1 = *(const float2*)(r1p + cb);
                    v00 += s0.x; v01 += s0.y;
                    v10 += s1.x; v11 += s1.y;
                }
                *(float2*)(Cout + (size_t)or0 * Nn + cb) = make_float2(v00, v01);
                *(float2*)(Cout + (size_t)or1 * Nn + cb) = make_float2(v10, v11);
            }
        }
    }
}

// ------------------------------- launcher -------------------------------------
extern "C" void kernel_launch(void* const* d_in, const int* in_sizes, int n_in,
                              void* d_out, int out_size)
{
    const float* x      = (const float*)d_in[0];
    const float* g1     = (const float*)d_in[1];
    const float* bn1    = (const float*)d_in[2];
    const float* w_qkv  = (const float*)d_in[3];
    const float* b_qkv  = (const float*)d_in[4];
    const float* w_proj = (const float*)d_in[5];
    const float* b_proj = (const float*)d_in[6];
    const float* g2     = (const float*)d_in[7];
    const float* bn2    = (const float*)d_in[8];
    const float* w_mlp1 = (const float*)d_in[9];
    const float* b_mlp1 = (const float*)d_in[10];
    const float* w_mlp2 = (const float*)d_in[11];
    const float* b_mlp2 = (const float*)d_in[12];
    float* out = (float*)d_out;

    uint16_t *ahi, *alo, *whi, *wlo;
    unsigned char* big;
    float* x2;
    cudaGetSymbolAddress((void**)&ahi, g_ahi);
    cudaGetSymbolAddress((void**)&alo, g_alo);
    cudaGetSymbolAddress((void**)&big, g_big);
    cudaGetSymbolAddress((void**)&x2,  g_x2);
    cudaGetSymbolAddress((void**)&whi, g_whi);
    cudaGetSymbolAddress((void**)&wlo, g_wlo);

    float* qkv = (float*)big;
    uint16_t* ghi = (uint16_t*)big;
    uint16_t* glo = (uint16_t*)(big + (size_t)NTOK * FDIM * 2);

    cudaFuncSetAttribute(hgemm<0>, cudaFuncAttributeMaxDynamicSharedMemorySize, SMEMB);
    cudaFuncSetAttribute(hgemm<1>, cudaFuncAttributeMaxDynamicSharedMemorySize, SMEMB);
    cudaFuncSetAttribute(hgemm<2>, cudaFuncAttributeMaxDynamicSharedMemorySize, SMEMB);
    cudaFuncSetAttribute(hgemm<3>, cudaFuncAttributeMaxDynamicSharedMemorySize, SMEMB);

    // 0) transpose+split weights to K-major bf16 hi/lo
    transpose_k<<<dim3(TDIM / 32, CC / 32), dim3(32, 8)>>>(w_qkv,  whi + WT_QKV,  wlo + WT_QKV,  CC, TDIM);
    transpose_k<<<dim3(CC / 32, CC / 32),   dim3(32, 8)>>>(w_proj, whi + WT_PROJ, wlo + WT_PROJ, CC, CC);
    transpose_k<<<dim3(FDIM / 32, CC / 32), dim3(32, 8)>>>(w_mlp1, whi + WT_MLP1, wlo + WT_MLP1, CC, FDIM);
    transpose_k<<<dim3(CC / 32, FDIM / 32), dim3(32, 8)>>>(w_mlp2, whi + WT_MLP2, wlo + WT_MLP2, FDIM, CC);

    // 1) LN1 + roll + window partition -> split A
    ln_kernel<<<NTOK, 128>>>(x, g1, bn1, ahi, alo, 1);

    // 2) QKV GEMM -> fp32 qkv
    hgemm<0><<<dim3(TDIM / 128, NTOK / 128), 256, SMEMB>>>(
        ahi, alo, whi + WT_QKV, wlo + WT_QKV, b_qkv, nullptr,
        qkv, nullptr, nullptr, TDIM, CC);

    // 3) attention -> split A
    attn_kernel<<<dim3(NWIN, NHEAD), 256>>>(qkv, ahi, alo);

    // 4) proj + scatter + shortcut -> fp32 x2
    hgemm<1><<<dim3(CC / 128, NTOK / 128), 256, SMEMB>>>(
        ahi, alo, whi + WT_PROJ, wlo + WT_PROJ, b_proj, x,
        x2, nullptr, nullptr, CC, CC);

    // 5) LN2 -> split A
    ln_kernel<<<NTOK, 128>>>(x2, g2, bn2, ahi, alo, 0);

    // 6) MLP1 + GELU -> split gelu
    hgemm<2><<<dim3(FDIM / 128, NTOK / 128), 256, SMEMB>>>(
        ahi, alo, whi + WT_MLP1, wlo + WT_MLP1, b_mlp1, nullptr,
        nullptr, ghi, glo, FDIM, CC);

    // 7) MLP2 + residual -> out
    hgemm<3><<<dim3(CC / 128, NTOK / 128), 256, SMEMB>>>(
        ghi, glo, whi + WT_MLP2, wlo + WT_MLP2, b_mlp2, x2,
        out, nullptr, nullptr, CC, FDIM);
}

// round 8
// speedup vs baseline: 2.6989x; 1.3778x over previous
#include <cuda_runtime.h>
#include <cuda_fp16.h>
#include <math.h>
#include <cstdint>

// Problem constants
#define BB    64
#define HH    56
#define CC    384
#define NHEAD 12
#define HDIM  32
#define WSZ   7
#define SSFT  3
#define LW    49
#define NWIN  4096
#define NTOK  200704
#define TDIM  1152
#define FDIM  1536

// ---------------- scratch ------------------------------------------------------
// A-operand fp16 hi (ln1 out -> attn out -> ln2 out)
__device__ uint16_t g_ahi[(size_t)NTOK * CC];
// union buffer: qkv fp32 (steps 2-3) OR gelu fp16 hi (steps 6-7)
__device__ __align__(16) unsigned char g_big[(size_t)NTOK * TDIM * 4];
// x2 residual fp32
__device__ float g_x2[(size_t)NTOK * CC];
// split weights fp16 hi/lo, K-major
__device__ uint16_t g_whi[1769472];
__device__ uint16_t g_wlo[1769472];
#define WT_QKV  0
#define WT_PROJ 442368
#define WT_MLP1 589824
#define WT_MLP2 1179648

// ---------------- helpers ------------------------------------------------------
__device__ __forceinline__ uint32_t smem_u32(const void* p) {
    uint32_t a;
    asm("{ .reg .u64 t; cvta.to.shared.u64 t, %1; cvt.u32.u64 %0, t; }" : "=r"(a) : "l"(p));
    return a;
}
#define LDSM4(r, a) \
    asm volatile("ldmatrix.sync.aligned.m8n8.x4.shared.b16 {%0,%1,%2,%3}, [%4];" \
        : "=r"((r)[0]), "=r"((r)[1]), "=r"((r)[2]), "=r"((r)[3]) : "r"(a))
#define MMA_F16(d, a, b) \
    asm volatile("mma.sync.aligned.m16n8k16.row.col.f32.f16.f16.f32 " \
        "{%0,%1,%2,%3},{%4,%5,%6,%7},{%8,%9},{%0,%1,%2,%3};" \
        : "+f"((d)[0]), "+f"((d)[1]), "+f"((d)[2]), "+f"((d)[3]) \
        : "r"((a)[0]), "r"((a)[1]), "r"((a)[2]), "r"((a)[3]), "r"((b)[0]), "r"((b)[1]))
#define CP16(d, s) do { \
    unsigned long long _g = __cvta_generic_to_global((const void*)(s)); \
    asm volatile("cp.async.cg.shared.global [%0], [%1], 16;" :: "r"(d), "l"(_g) : "memory"); \
} while (0)
#define CP_COMMIT() asm volatile("cp.async.commit_group;" ::: "memory")
#define CP_WAIT1()  asm volatile("cp.async.wait_group 1;" ::: "memory")

__device__ __forceinline__ int map_row(int r) {
    int n = r / LW, l = r - n * LW;
    int b = n >> 6, w = n & 63;
    int wh = w >> 3, ww = w & 7;
    int i = l / WSZ, j = l - i * WSZ;
    int hh = wh * WSZ + i, hw = ww * WSZ + j;
    int oh = hh + SSFT; if (oh >= HH) oh -= HH;
    int ow = hw + SSFT; if (ow >= HH) ow -= HH;
    return b * (HH * HH) + oh * HH + ow;
}
__device__ __forceinline__ float gelu_f(float x) {
    return 0.5f * x * (1.0f + erff(x * 0.7071067811865476f));
}
__device__ __forceinline__ uint16_t h_bits(__half h) { return *(uint16_t*)&h; }
__device__ __forceinline__ uint16_t f2h_hi(float v) { return h_bits(__float2half_rn(v)); }
__device__ __forceinline__ void split_h(float v, uint16_t& hi, uint16_t& lo) {
    __half h = __float2half_rn(v);
    hi = h_bits(h);
    lo = h_bits(__float2half_rn(v - __half2float(h)));
}
// swizzled byte offset within an 8KB tile (128 rows x 64B)
__device__ __forceinline__ uint32_t swz(uint32_t row, uint32_t cb2) {
    return row * 64 + ((cb2 ^ ((row >> 1) & 3)) << 4);
}

// ---------------- weight transpose + split: [K][N] fp32 -> [N][K] fp16 hi/lo ---
__global__ void transpose_k(const float* __restrict__ src,
                            uint16_t* __restrict__ dhi, uint16_t* __restrict__ dlo,
                            int K, int N)
{
    __shared__ float t[32][33];
    int kb = blockIdx.y * 32, nb = blockIdx.x * 32;
    int tx = threadIdx.x, ty = threadIdx.y;  // 32x8
    #pragma unroll
    for (int i = ty; i < 32; i += 8) t[i][tx] = src[(size_t)(kb + i) * N + nb + tx];
    __syncthreads();
    #pragma unroll
    for (int i = ty; i < 32; i += 8) {
        uint16_t hi, lo;
        split_h(t[tx][i], hi, lo);
        size_t idx = (size_t)(nb + i) * K + kb + tx;
        dhi[idx] = hi;
        dlo[idx] = lo;
    }
}

// ---------------- LayerNorm -> fp16 hi -----------------------------------------
__global__ void ln_kernel(const float* __restrict__ x,
                          const float* __restrict__ gw,
                          const float* __restrict__ bw,
                          uint16_t* __restrict__ ohi, int gather)
{
    int r = blockIdx.x;
    int tid = threadIdx.x;
    int src = gather ? map_row(r) : r;
    const float* xr = x + (size_t)src * CC;
    float v0 = xr[tid], v1 = xr[tid + 128], v2 = xr[tid + 256];
    float s = v0 + v1 + v2;
    float q = v0 * v0 + v1 * v1 + v2 * v2;
    #pragma unroll
    for (int o = 16; o; o >>= 1) {
        s += __shfl_xor_sync(0xffffffffu, s, o);
        q += __shfl_xor_sync(0xffffffffu, q, o);
    }
    __shared__ float ss[4], sq[4];
    int w = tid >> 5;
    if ((tid & 31) == 0) { ss[w] = s; sq[w] = q; }
    __syncthreads();
    s = ss[0] + ss[1] + ss[2] + ss[3];
    q = sq[0] + sq[1] + sq[2] + sq[3];
    float mean = s * (1.0f / CC);
    float var  = q * (1.0f / CC) - mean * mean;
    float rstd = rsqrtf(var + 1e-5f);
    size_t base = (size_t)r * CC;
    #pragma unroll
    for (int e = 0; e < 3; e++) {
        int col = tid + e * 128;
        float v = (e == 0 ? v0 : (e == 1 ? v1 : v2));
        ohi[base + col] = f2h_hi((v - mean) * rstd * gw[col] + bw[col]);
    }
}

// ---------------- windowed attention: thread-per-row, broadcast LDS ------------
__global__ __launch_bounds__(64) void attn_kernel(const float* __restrict__ qkv,
                                                  uint16_t* __restrict__ ohi)
{
    int n = blockIdx.x, h = blockIdx.y;
    __shared__ float qs[LW][HDIM + 1];
    __shared__ float ks[LW][HDIM + 1];
    __shared__ float vs[LW][HDIM + 1];
    __shared__ float sc[LW][51];
    __shared__ int   rg[LW];
    int tid = threadIdx.x;

    size_t base = (size_t)n * LW * TDIM + h * HDIM;
    for (int i = tid; i < LW * HDIM; i += 64) {
        int l = i >> 5, d = i & 31;
        size_t p = base + (size_t)l * TDIM + d;
        qs[l][d] = qkv[p];
        ks[l][d] = qkv[p + CC];
        vs[l][d] = qkv[p + 2 * CC];
    }
    if (tid < LW) {
        int w = n & 63;
        int wh = w >> 3, ww = w & 7;
        int i = tid / WSZ, j = tid - i * WSZ;
        int hh = wh * WSZ + i, hw = ww * WSZ + j;
        int rh = hh < 49 ? 0 : (hh < 53 ? 1 : 2);
        int rw = hw < 49 ? 0 : (hw < 53 ? 1 : 2);
        rg[tid] = rh * 3 + rw;
    }
    __syncthreads();

    int l = tid;
    if (l < LW) {
        const float scale = 0.17677669529663687f;
        float q[HDIM];
        #pragma unroll
        for (int d = 0; d < HDIM; d++) q[d] = qs[l][d];
        int rl = rg[l];

        float mx = -1e30f;
        for (int m = 0; m < LW; m++) {
            float acc = 0.0f;
            #pragma unroll
            for (int d = 0; d < HDIM; d++) acc += q[d] * ks[m][d];   // broadcast LDS
            acc = acc * scale + (rl == rg[m] ? 0.0f : -100.0f);
            sc[l][m] = acc;
            mx = fmaxf(mx, acc);
        }
        float sum = 0.0f;
        for (int m = 0; m < LW; m++) {
            float e = expf(sc[l][m] - mx);
            sc[l][m] = e;
            sum += e;
        }
        float inv = 1.0f / sum;

        float o[HDIM];
        #pragma unroll
        for (int d = 0; d < HDIM; d++) o[d] = 0.0f;
        for (int m = 0; m < LW; m++) {
            float p = sc[l][m] * inv;
            #pragma unroll
            for (int d = 0; d < HDIM; d++) o[d] += p * vs[m][d];     // broadcast LDS
        }
        uint16_t* op = ohi + (size_t)(n * LW + l) * CC + h * HDIM;
        #pragma unroll
        for (int d = 0; d < HDIM; d += 2) {
            __half2 hv = __floats2half2_rn(o[d], o[d + 1]);
            *(uint32_t*)(op + d) = *(uint32_t*)&hv;
        }
    }
}

// ---------------- fp16 2-product mma.sync GEMM 128x128x32, cp.async 3-stage ----
// stage layout: Ah[8KB] Bh[8KB] Bl[8KB] = 24KB; 3 stages = 72KB
#define TILE8K 8192
#define STAGEB 24576
#define SMEMB  73728

// EPI 0: fp32 out = acc + bias                       (QKV)
// EPI 1: fp32 out[map_row] = resid[map_row]+acc+bias (proj scatter)
// EPI 2: fp16-hi out = gelu(acc + bias)              (MLP1)
// EPI 3: fp32 out = acc + bias + resid               (MLP2 final)
template<int EPI>
__global__ __launch_bounds__(256) void hgemm(
    const uint16_t* __restrict__ Ah,
    const uint16_t* __restrict__ Bh, const uint16_t* __restrict__ Bl,
    const float* __restrict__ bias, const float* __restrict__ resid,
    float* __restrict__ Cout, uint16_t* __restrict__ OutHi,
    int Nn, int K)
{
    extern __shared__ char smem[];
    uint32_t sb = smem_u32(smem);
    int tid = threadIdx.x;
    int lane = tid & 31, warp = tid >> 5;
    int wm = warp >> 2, wn = warp & 3;        // warp tile: 64(m) x 32(n)
    int m0 = blockIdx.y * 128, n0 = blockIdx.x * 128;

    const uint16_t* srcs[3] = {
        Ah + (size_t)m0 * K,
        Bh + (size_t)n0 * K, Bl + (size_t)n0 * K
    };

    float acc[4][4][4];
    #pragma unroll
    for (int i = 0; i < 4; i++)
        #pragma unroll
        for (int j = 0; j < 4; j++)
            #pragma unroll
            for (int e = 0; e < 4; e++) acc[i][j][e] = 0.0f;

    int NC = K / 32;

    auto load_stage = [&](int stg, int c) {
        uint32_t sdst = sb + stg * STAGEB;
        #pragma unroll
        for (int i = 0; i < 6; i++) {
            int tile = i >> 1;
            int w = tid + ((i & 1) << 8);
            int r = w >> 2, cb = w & 3;
            uint32_t d = sdst + tile * TILE8K + swz(r, cb);
            const uint16_t* s = srcs[tile] + (size_t)r * K + c * 32 + cb * 8;
            CP16(d, s);
        }
        CP_COMMIT();
    };

    load_stage(0, 0);
    load_stage(1, 1);

    int cs = 0;
    for (int c = 0; c < NC; c++) {
        CP_WAIT1();
        __syncthreads();
        if (c + 2 < NC) {
            int s2 = cs + 2; if (s2 >= 3) s2 -= 3;
            load_stage(s2, c + 2);
        }
        uint32_t sbs = sb + cs * STAGEB;
        #pragma unroll
        for (int kk = 0; kk < 2; kk++) {
            uint32_t cb2 = (uint32_t)(kk * 2 + (lane >> 4));
            uint32_t ah[4][4];
            #pragma unroll
            for (int i = 0; i < 4; i++) {
                uint32_t row = (uint32_t)(wm * 64 + i * 16 + (lane & 15));
                LDSM4(ah[i], sbs + swz(row, cb2));
            }
            uint32_t bh[4][2], bl[4][2];
            #pragma unroll
            for (int g = 0; g < 2; g++) {
                uint32_t row = (uint32_t)(wn * 32 + g * 16 + (lane & 15));
                uint32_t r[4];
                LDSM4(r, sbs + TILE8K + swz(row, cb2));
                bh[2 * g][0] = r[0]; bh[2 * g][1] = r[2];
                bh[2 * g + 1][0] = r[1]; bh[2 * g + 1][1] = r[3];
                LDSM4(r, sbs + 2 * TILE8K + swz(row, cb2));
                bl[2 * g][0] = r[0]; bl[2 * g][1] = r[2];
                bl[2 * g + 1][0] = r[1]; bl[2 * g + 1][1] = r[3];
            }
            #pragma unroll
            for (int i = 0; i < 4; i++)
                #pragma unroll
                for (int j = 0; j < 4; j++)
                    MMA_F16(acc[i][j], ah[i], bh[j]);
            #pragma unroll
            for (int i = 0; i < 4; i++)
                #pragma unroll
                for (int j = 0; j < 4; j++)
                    MMA_F16(acc[i][j], ah[i], bl[j]);
        }
        cs++; if (cs >= 3) cs = 0;
    }

    // ---- epilogue ----
    int lr = lane >> 2;
    int lc = (lane & 3) * 2;
    #pragma unroll
    for (int i = 0; i < 4; i++) {
        int gr0 = m0 + wm * 64 + i * 16 + lr;
        int gr1 = gr0 + 8;
        int or0 = (EPI == 1) ? map_row(gr0) : gr0;
        int or1 = (EPI == 1) ? map_row(gr1) : gr1;
        const float* r0p = (EPI == 1 || EPI == 3) ? resid + (size_t)or0 * Nn : nullptr;
        const float* r1p = (EPI == 1 || EPI == 3) ? resid + (size_t)or1 * Nn : nullptr;
        #pragma unroll
        for (int j = 0; j < 4; j++) {
            int cb = n0 + wn * 32 + j * 8 + lc;
            float b0 = bias[cb], b1 = bias[cb + 1];
            float v00 = acc[i][j][0] + b0, v01 = acc[i][j][1] + b1;
            float v10 = acc[i][j][2] + b0, v11 = acc[i][j][3] + b1;
            if (EPI == 2) {
                v00 = gelu_f(v00); v01 = gelu_f(v01);
                v10 = gelu_f(v10); v11 = gelu_f(v11);
                *(uint32_t*)(OutHi + (size_t)or0 * Nn + cb) =
                    (uint32_t)f2h_hi(v00) | ((uint32_t)f2h_hi(v01) << 16);
                *(uint32_t*)(OutHi + (size_t)or1 * Nn + cb) =
                    (uint32_t)f2h_hi(v10) | ((uint32_t)f2h_hi(v11) << 16);
            } else {
                if (EPI == 1 || EPI == 3) {
                    float2 s0 = *(const float2*)(r0p + cb);
                    float2 s1 = *(const float2*)(r1p + cb);
                    v00 += s0.x; v01 += s0.y;
                    v10 += s1.x; v11 += s1.y;
                }
                *(float2*)(Cout + (size_t)or0 * Nn + cb) = make_float2(v00, v01);
                *(float2*)(Cout + (size_t)or1 * Nn + cb) = make_float2(v10, v11);
            }
        }
    }
}

// ------------------------------- launcher -------------------------------------
extern "C" void kernel_launch(void* const* d_in, const int* in_sizes, int n_in,
                              void* d_out, int out_size)
{
    const float* x      = (const float*)d_in[0];
    const float* g1     = (const float*)d_in[1];
    const float* bn1    = (const float*)d_in[2];
    const float* w_qkv  = (const float*)d_in[3];
    const float* b_qkv  = (const float*)d_in[4];
    const float* w_proj = (const float*)d_in[5];
    const float* b_proj = (const float*)d_in[6];
    const float* g2     = (const float*)d_in[7];
    const float* bn2    = (const float*)d_in[8];
    const float* w_mlp1 = (const float*)d_in[9];
    const float* b_mlp1 = (const float*)d_in[10];
    const float* w_mlp2 = (const float*)d_in[11];
    const float* b_mlp2 = (const float*)d_in[12];
    float* out = (float*)d_out;

    uint16_t *ahi, *whi, *wlo;
    unsigned char* big;
    float* x2;
    cudaGetSymbolAddress((void**)&ahi, g_ahi);
    cudaGetSymbolAddress((void**)&big, g_big);
    cudaGetSymbolAddress((void**)&x2,  g_x2);
    cudaGetSymbolAddress((void**)&whi, g_whi);
    cudaGetSymbolAddress((void**)&wlo, g_wlo);

    float* qkv = (float*)big;
    uint16_t* ghi = (uint16_t*)big;

    cudaFuncSetAttribute(hgemm<0>, cudaFuncAttributeMaxDynamicSharedMemorySize, SMEMB);
    cudaFuncSetAttribute(hgemm<1>, cudaFuncAttributeMaxDynamicSharedMemorySize, SMEMB);
    cudaFuncSetAttribute(hgemm<2>, cudaFuncAttributeMaxDynamicSharedMemorySize, SMEMB);
    cudaFuncSetAttribute(hgemm<3>, cudaFuncAttributeMaxDynamicSharedMemorySize, SMEMB);

    // 0) transpose+split weights to K-major fp16 hi/lo
    transpose_k<<<dim3(TDIM / 32, CC / 32), dim3(32, 8)>>>(w_qkv,  whi + WT_QKV,  wlo + WT_QKV,  CC, TDIM);
    transpose_k<<<dim3(CC / 32, CC / 32),   dim3(32, 8)>>>(w_proj, whi + WT_PROJ, wlo + WT_PROJ, CC, CC);
    transpose_k<<<dim3(FDIM / 32, CC / 32), dim3(32, 8)>>>(w_mlp1, whi + WT_MLP1, wlo + WT_MLP1, CC, FDIM);
    transpose_k<<<dim3(CC / 32, FDIM / 32), dim3(32, 8)>>>(w_mlp2, whi + WT_MLP2, wlo + WT_MLP2, FDIM, CC);

    // 1) LN1 + roll + window partition -> A hi
    ln_kernel<<<NTOK, 128>>>(x, g1, bn1, ahi, 1);

    // 2) QKV GEMM -> fp32 qkv
    hgemm<0><<<dim3(TDIM / 128, NTOK / 128), 256, SMEMB>>>(
        ahi, whi + WT_QKV, wlo + WT_QKV, b_qkv, nullptr,
        qkv, nullptr, TDIM, CC);

    // 3) attention -> A hi
    attn_kernel<<<dim3(NWIN, NHEAD), 64>>>(qkv, ahi);

    // 4) proj + scatter + shortcut -> fp32 x2
    hgemm<1><<<dim3(CC / 128, NTOK / 128), 256, SMEMB>>>(
        ahi, whi + WT_PROJ, wlo + WT_PROJ, b_proj, x,
        x2, nullptr, CC, CC);

    // 5) LN2 -> A hi
    ln_kernel<<<NTOK, 128>>>(x2, g2, bn2, ahi, 0);

    // 6) MLP1 + GELU -> fp16 hi (aliases qkv, dead by now)
    hgemm<2><<<dim3(FDIM / 128, NTOK / 128), 256, SMEMB>>>(
        ahi, whi + WT_MLP1, wlo + WT_MLP1, b_mlp1, nullptr,
        nullptr, ghi, FDIM, CC);

    // 7) MLP2 + residual -> out
    hgemm<3><<<dim3(CC / 128, NTOK / 128), 256, SMEMB>>>(
        ghi, whi + WT_MLP2, wlo + WT_MLP2, b_mlp2, x2,
        out, nullptr, CC, FDIM);
}

// round 14
// speedup vs baseline: 3.7740x; 1.3983x over previous
#include <cuda_runtime.h>
#include <cuda_fp16.h>
#include <math.h>
#include <cstdint>

// Problem constants
#define BB    64
#define HH    56
#define CC    384
#define NHEAD 12
#define HDIM  32
#define WSZ   7
#define SSFT  3
#define LW    49
#define NWIN  4096
#define NTOK  200704
#define TDIM  1152
#define FDIM  1536

// ---------------- scratch ------------------------------------------------------
__device__ uint16_t g_ahi[(size_t)NTOK * CC];            // A operand fp16
__device__ __align__(16) unsigned char g_big[(size_t)NTOK * TDIM * 4];  // qkv fp32 | gelu fp16
__device__ float g_x2[(size_t)NTOK * CC];                // x2 residual fp32
__device__ uint16_t g_whi[1769472];                      // weights fp16, K-major
#define WT_QKV  0
#define WT_PROJ 442368
#define WT_MLP1 589824
#define WT_MLP2 1179648

// ---------------- helpers ------------------------------------------------------
__device__ __forceinline__ uint32_t smem_u32(const void* p) {
    uint32_t a;
    asm("{ .reg .u64 t; cvta.to.shared.u64 t, %1; cvt.u32.u64 %0, t; }" : "=r"(a) : "l"(p));
    return a;
}
#define LDSM4(r, a) \
    asm volatile("ldmatrix.sync.aligned.m8n8.x4.shared.b16 {%0,%1,%2,%3}, [%4];" \
        : "=r"((r)[0]), "=r"((r)[1]), "=r"((r)[2]), "=r"((r)[3]) : "r"(a))
#define MMA_F16(d, a, b) \
    asm volatile("mma.sync.aligned.m16n8k16.row.col.f32.f16.f16.f32 " \
        "{%0,%1,%2,%3},{%4,%5,%6,%7},{%8,%9},{%0,%1,%2,%3};" \
        : "+f"((d)[0]), "+f"((d)[1]), "+f"((d)[2]), "+f"((d)[3]) \
        : "r"((a)[0]), "r"((a)[1]), "r"((a)[2]), "r"((a)[3]), "r"((b)[0]), "r"((b)[1]))
#define CP16(d, s) do { \
    unsigned long long _g = __cvta_generic_to_global((const void*)(s)); \
    asm volatile("cp.async.cg.shared.global [%0], [%1], 16;" :: "r"(d), "l"(_g) : "memory"); \
} while (0)
#define CP_COMMIT() asm volatile("cp.async.commit_group;" ::: "memory")
#define CP_WAIT1()  asm volatile("cp.async.wait_group 1;" ::: "memory")

__device__ __forceinline__ int map_row(int r) {
    int n = r / LW, l = r - n * LW;
    int b = n >> 6, w = n & 63;
    int wh = w >> 3, ww = w & 7;
    int i = l / WSZ, j = l - i * WSZ;
    int hh = wh * WSZ + i, hw = ww * WSZ + j;
    int oh = hh + SSFT; if (oh >= HH) oh -= HH;
    int ow = hw + SSFT; if (ow >= HH) ow -= HH;
    return b * (HH * HH) + oh * HH + ow;
}
__device__ __forceinline__ float gelu_f(float x) {
    return 0.5f * x * (1.0f + erff(x * 0.7071067811865476f));
}
__device__ __forceinline__ uint16_t f2h_hi(float v) {
    __half h = __float2half_rn(v);
    return *(uint16_t*)&h;
}
// swizzled byte offset within an 8KB tile (128 rows x 64B)
__device__ __forceinline__ uint32_t swz(uint32_t row, uint32_t cb2) {
    return row * 64 + ((cb2 ^ ((row >> 1) & 3)) << 4);
}

// ---------------- weight transpose: [K][N] fp32 -> [N][K] fp16 -----------------
__global__ void transpose_k(const float* __restrict__ src,
                            uint16_t* __restrict__ dhi, int K, int N)
{
    __shared__ float t[32][33];
    int kb = blockIdx.y * 32, nb = blockIdx.x * 32;
    int tx = threadIdx.x, ty = threadIdx.y;  // 32x8
    #pragma unroll
    for (int i = ty; i < 32; i += 8) t[i][tx] = src[(size_t)(kb + i) * N + nb + tx];
    __syncthreads();
    #pragma unroll
    for (int i = ty; i < 32; i += 8)
        dhi[(size_t)(nb + i) * K + kb + tx] = f2h_hi(t[tx][i]);
}

// ---------------- LayerNorm -> fp16 --------------------------------------------
__global__ void ln_kernel(const float* __restrict__ x,
                          const float* __restrict__ gw,
                          const float* __restrict__ bw,
                          uint16_t* __restrict__ ohi, int gather)
{
    int r = blockIdx.x;
    int tid = threadIdx.x;
    int src = gather ? map_row(r) : r;
    const float* xr = x + (size_t)src * CC;
    float v0 = xr[tid], v1 = xr[tid + 128], v2 = xr[tid + 256];
    float s = v0 + v1 + v2;
    float q = v0 * v0 + v1 * v1 + v2 * v2;
    #pragma unroll
    for (int o = 16; o; o >>= 1) {
        s += __shfl_xor_sync(0xffffffffu, s, o);
        q += __shfl_xor_sync(0xffffffffu, q, o);
    }
    __shared__ float ss[4], sq[4];
    int w = tid >> 5;
    if ((tid & 31) == 0) { ss[w] = s; sq[w] = q; }
    __syncthreads();
    s = ss[0] + ss[1] + ss[2] + ss[3];
    q = sq[0] + sq[1] + sq[2] + sq[3];
    float mean = s * (1.0f / CC);
    float var  = q * (1.0f / CC) - mean * mean;
    float rstd = rsqrtf(var + 1e-5f);
    size_t base = (size_t)r * CC;
    #pragma unroll
    for (int e = 0; e < 3; e++) {
        int col = tid + e * 128;
        float v = (e == 0 ? v0 : (e == 1 ? v1 : v2));
        ohi[base + col] = f2h_hi((v - mean) * rstd * gw[col] + bw[col]);
    }
}

// ---------------- windowed attention: thread-per-row, broadcast LDS ------------
__global__ __launch_bounds__(64) void attn_kernel(const float* __restrict__ qkv,
                                                  uint16_t* __restrict__ ohi)
{
    int n = blockIdx.x, h = blockIdx.y;
    __shared__ float qs[LW][HDIM + 1];
    __shared__ float ks[LW][HDIM + 1];
    __shared__ float vs[LW][HDIM + 1];
    __shared__ float sc[LW][51];
    __shared__ int   rg[LW];
    int tid = threadIdx.x;

    size_t base = (size_t)n * LW * TDIM + h * HDIM;
    for (int i = tid; i < LW * HDIM; i += 64) {
        int l = i >> 5, d = i & 31;
        size_t p = base + (size_t)l * TDIM + d;
        qs[l][d] = qkv[p];
        ks[l][d] = qkv[p + CC];
        vs[l][d] = qkv[p + 2 * CC];
    }
    if (tid < LW) {
        int w = n & 63;
        int wh = w >> 3, ww = w & 7;
        int i = tid / WSZ, j = tid - i * WSZ;
        int hh = wh * WSZ + i, hw = ww * WSZ + j;
        int rh = hh < 49 ? 0 : (hh < 53 ? 1 : 2);
        int rw = hw < 49 ? 0 : (hw < 53 ? 1 : 2);
        rg[tid] = rh * 3 + rw;
    }
    __syncthreads();

    int l = tid;
    if (l < LW) {
        const float scale = 0.17677669529663687f;
        float q[HDIM];
        #pragma unroll
        for (int d = 0; d < HDIM; d++) q[d] = qs[l][d];
        int rl = rg[l];

        float mx = -1e30f;
        for (int m = 0; m < LW; m++) {
            float acc = 0.0f;
            #pragma unroll
            for (int d = 0; d < HDIM; d++) acc += q[d] * ks[m][d];
            acc = acc * scale + (rl == rg[m] ? 0.0f : -100.0f);
            sc[l][m] = acc;
            mx = fmaxf(mx, acc);
        }
        float sum = 0.0f;
        for (int m = 0; m < LW; m++) {
            float e = expf(sc[l][m] - mx);
            sc[l][m] = e;
            sum += e;
        }
        float inv = 1.0f / sum;

        float o[HDIM];
        #pragma unroll
        for (int d = 0; d < HDIM; d++) o[d] = 0.0f;
        for (int m = 0; m < LW; m++) {
            float p = sc[l][m] * inv;
            #pragma unroll
            for (int d = 0; d < HDIM; d++) o[d] += p * vs[m][d];
        }
        uint16_t* op = ohi + (size_t)(n * LW + l) * CC + h * HDIM;
        #pragma unroll
        for (int d = 0; d < HDIM; d += 2) {
            __half2 hv = __floats2half2_rn(o[d], o[d + 1]);
            *(uint32_t*)(op + d) = *(uint32_t*)&hv;
        }
    }
}

// ---------------- fp16 single-product mma.sync GEMM 128x128x32, 3-stage --------
// stage layout: Ah[8KB] Bh[8KB] = 16KB; 3 stages = 48KB
#define TILE8K 8192
#define STAGEB 16384
#define SMEMB  49152

// EPI 0: fp32 out = acc + bias
// EPI 1: fp32 out[map_row] = resid[map_row]+acc+bias
// EPI 2: fp16 out = gelu(acc + bias)
// EPI 3: fp32 out = acc + bias + resid
template<int EPI>
__global__ __launch_bounds__(256) void hgemm(
    const uint16_t* __restrict__ Ah, const uint16_t* __restrict__ Bh,
    const float* __restrict__ bias, const float* __restrict__ resid,
    float* __restrict__ Cout, uint16_t* __restrict__ OutHi,
    int Nn, int K)
{
    extern __shared__ char smem[];
    uint32_t sb = smem_u32(smem);
    int tid = threadIdx.x;
    int lane = tid & 31, warp = tid >> 5;
    int wm = warp >> 2, wn = warp & 3;        // warp tile: 64(m) x 32(n)
    int m0 = blockIdx.y * 128, n0 = blockIdx.x * 128;

    const uint16_t* srcA = Ah + (size_t)m0 * K;
    const uint16_t* srcB = Bh + (size_t)n0 * K;

    float acc[4][4][4];
    #pragma unroll
    for (int i = 0; i < 4; i++)
        #pragma unroll
        for (int j = 0; j < 4; j++)
            #pragma unroll
            for (int e = 0; e < 4; e++) acc[i][j][e] = 0.0f;

    int NC = K / 32;

    auto load_stage = [&](int stg, int c) {
        uint32_t sdst = sb + stg * STAGEB;
        #pragma unroll
        for (int i = 0; i < 4; i++) {
            int tile = i >> 1;
            int w = tid + ((i & 1) << 8);
            int r = w >> 2, cb = w & 3;
            uint32_t d = sdst + tile * TILE8K + swz(r, cb);
            const uint16_t* s = (tile ? srcB : srcA) + (size_t)r * K + c * 32 + cb * 8;
            CP16(d, s);
        }
        CP_COMMIT();
    };

    load_stage(0, 0);
    load_stage(1, 1);

    int cs = 0;
    for (int c = 0; c < NC; c++) {
        CP_WAIT1();
        __syncthreads();
        if (c + 2 < NC) {
            int s2 = cs + 2; if (s2 >= 3) s2 -= 3;
            load_stage(s2, c + 2);
        }
        uint32_t sbs = sb + cs * STAGEB;
        #pragma unroll
        for (int kk = 0; kk < 2; kk++) {
            uint32_t cb2 = (uint32_t)(kk * 2 + (lane >> 4));
            uint32_t ah[4][4];
            #pragma unroll
            for (int i = 0; i < 4; i++) {
                uint32_t row = (uint32_t)(wm * 64 + i * 16 + (lane & 15));
                LDSM4(ah[i], sbs + swz(row, cb2));
            }
            uint32_t bh[4][2];
            #pragma unroll
            for (int g = 0; g < 2; g++) {
                uint32_t row = (uint32_t)(wn * 32 + g * 16 + (lane & 15));
                uint32_t r[4];
                LDSM4(r, sbs + TILE8K + swz(row, cb2));
                bh[2 * g][0] = r[0]; bh[2 * g][1] = r[2];
                bh[2 * g + 1][0] = r[1]; bh[2 * g + 1][1] = r[3];
            }
            #pragma unroll
            for (int i = 0; i < 4; i++)
                #pragma unroll
                for (int j = 0; j < 4; j++)
                    MMA_F16(acc[i][j], ah[i], bh[j]);
        }
        cs++; if (cs >= 3) cs = 0;
    }

    // ---- epilogue ----
    int lr = lane >> 2;
    int lc = (lane & 3) * 2;
    #pragma unroll
    for (int i = 0; i < 4; i++) {
        int gr0 = m0 + wm * 64 + i * 16 + lr;
        int gr1 = gr0 + 8;
        int or0 = (EPI == 1) ? map_row(gr0) : gr0;
        int or1 = (EPI == 1) ? map_row(gr1) : gr1;
        const float* r0p = (EPI == 1 || EPI == 3) ? resid + (size_t)or0 * Nn : nullptr;
        const float* r1p = (EPI == 1 || EPI == 3) ? resid + (size_t)or1 * Nn : nullptr;
        #pragma unroll
        for (int j = 0; j < 4; j++) {
            int cb = n0 + wn * 32 + j * 8 + lc;
            float b0 = bias[cb], b1 = bias[cb + 1];
            float v00 = acc[i][j][0] + b0, v01 = acc[i][j][1] + b1;
            float v10 = acc[i][j][2] + b0, v11 = acc[i][j][3] + b1;
            if (EPI == 2) {
                v00 = gelu_f(v00); v01 = gelu_f(v01);
                v10 = gelu_f(v10); v11 = gelu_f(v11);
                *(uint32_t*)(OutHi + (size_t)or0 * Nn + cb) =
                    (uint32_t)f2h_hi(v00) | ((uint32_t)f2h_hi(v01) << 16);
                *(uint32_t*)(OutHi + (size_t)or1 * Nn + cb) =
                    (uint32_t)f2h_hi(v10) | ((uint32_t)f2h_hi(v11) << 16);
            } else {
                if (EPI == 1 || EPI == 3) {
                    float2 s0 = *(const float2*)(r0p + cb);
                    float2 s1 = *(const float2*)(r1p + cb);
                    v00 += s0.x; v01 += s0.y;
                    v10 += s1.x; v11 += s1.y;
                }
                *(float2*)(Cout + (size_t)or0 * Nn + cb) = make_float2(v00, v01);
                *(float2*)(Cout + (size_t)or1 * Nn + cb) = make_float2(v10, v11);
            }
        }
    }
}

// ------------------------------- launcher -------------------------------------
extern "C" void kernel_launch(void* const* d_in, const int* in_sizes, int n_in,
                              void* d_out, int out_size)
{
    const float* x      = (const float*)d_in[0];
    const float* g1     = (const float*)d_in[1];
    const float* bn1    = (const float*)d_in[2];
    const float* w_qkv  = (const float*)d_in[3];
    const float* b_qkv  = (const float*)d_in[4];
    const float* w_proj = (const float*)d_in[5];
    const float* b_proj = (const float*)d_in[6];
    const float* g2     = (const float*)d_in[7];
    const float* bn2    = (const float*)d_in[8];
    const float* w_mlp1 = (const float*)d_in[9];
    const float* b_mlp1 = (const float*)d_in[10];
    const float* w_mlp2 = (const float*)d_in[11];
    const float* b_mlp2 = (const float*)d_in[12];
    float* out = (float*)d_out;

    uint16_t *ahi, *whi;
    unsigned char* big;
    float* x2;
    cudaGetSymbolAddress((void**)&ahi, g_ahi);
    cudaGetSymbolAddress((void**)&big, g_big);
    cudaGetSymbolAddress((void**)&x2,  g_x2);
    cudaGetSymbolAddress((void**)&whi, g_whi);

    float* qkv = (float*)big;
    uint16_t* ghi = (uint16_t*)big;

    cudaFuncSetAttribute(hgemm<0>, cudaFuncAttributeMaxDynamicSharedMemorySize, SMEMB);
    cudaFuncSetAttribute(hgemm<1>, cudaFuncAttributeMaxDynamicSharedMemorySize, SMEMB);
    cudaFuncSetAttribute(hgemm<2>, cudaFuncAttributeMaxDynamicSharedMemorySize, SMEMB);
    cudaFuncSetAttribute(hgemm<3>, cudaFuncAttributeMaxDynamicSharedMemorySize, SMEMB);

    // 0) transpose weights to K-major fp16
    transpose_k<<<dim3(TDIM / 32, CC / 32), dim3(32, 8)>>>(w_qkv,  whi + WT_QKV,  CC, TDIM);
    transpose_k<<<dim3(CC / 32, CC / 32),   dim3(32, 8)>>>(w_proj, whi + WT_PROJ, CC, CC);
    transpose_k<<<dim3(FDIM / 32, CC / 32), dim3(32, 8)>>>(w_mlp1, whi + WT_MLP1, CC, FDIM);
    transpose_k<<<dim3(CC / 32, FDIM / 32), dim3(32, 8)>>>(w_mlp2, whi + WT_MLP2, FDIM, CC);

    // 1) LN1 + roll + window partition -> A fp16
    ln_kernel<<<NTOK, 128>>>(x, g1, bn1, ahi, 1);

    // 2) QKV GEMM -> fp32 qkv
    hgemm<0><<<dim3(TDIM / 128, NTOK / 128), 256, SMEMB>>>(
        ahi, whi + WT_QKV, b_qkv, nullptr, qkv, nullptr, TDIM, CC);

    // 3) attention -> A fp16
    attn_kernel<<<dim3(NWIN, NHEAD), 64>>>(qkv, ahi);

    // 4) proj + scatter + shortcut -> fp32 x2
    hgemm<1><<<dim3(CC / 128, NTOK / 128), 256, SMEMB>>>(
        ahi, whi + WT_PROJ, b_proj, x, x2, nullptr, CC, CC);

    // 5) LN2 -> A fp16
    ln_kernel<<<NTOK, 128>>>(x2, g2, bn2, ahi, 0);

    // 6) MLP1 + GELU -> fp16 (aliases qkv, dead by now)
    hgemm<2><<<dim3(FDIM / 128, NTOK / 128), 256, SMEMB>>>(
        ahi, whi + WT_MLP1, b_mlp1, nullptr, nullptr, ghi, FDIM, CC);

    // 7) MLP2 + residual -> out
    hgemm<3><<<dim3(CC / 128, NTOK / 128), 256, SMEMB>>>(
        ghi, whi + WT_MLP2, b_mlp2, x2, out, nullptr, CC, FDIM);
}